// round 4
// baseline (speedup 1.0000x reference)
#include <cuda_runtime.h>
#include <cuda_bf16.h>

// Problem constants
#define BB 16
#define TT 24
#define NN 2048
#define FF 64
#define BT (BB*TT)          // 384
#define NF (NN*FF)          // 131072
#define NF2 (NF/2)          // 65536 float2 per (b,t) row
#define KSPLIT 8

// Scratch (device globals; no allocation allowed). All fully overwritten each call.
__device__ float d_rhs[BT*NN];        // 3 MB
__device__ float d_lf [BT*FF];        // lhs_f
__device__ float d_Gp [KSPLIT*BT*FF]; // K-split partials of G
__device__ float d_A  [BB*TT*TT];     // attention weights

// ---------------------------------------------------------------------------
// Kernel 1: one pass over x per (b,t) block.
//   rhs[n]   = sum_f x[n,f]*U3[f]
//   lhs_f[f] = sum_n x[n,f]*U1[n]
// Warp layout: 8 rows per iteration; 4 lanes per row (r = lane>>2, q = lane&3).
// ---------------------------------------------------------------------------
__global__ __launch_bounds__(256) void k1_pass(
    const float* __restrict__ x, const float* __restrict__ U1,
    const float* __restrict__ U3, float* __restrict__ rhs, float* __restrict__ lf)
{
    const int bt   = blockIdx.x;
    const int w    = threadIdx.x >> 5;
    const int lane = threadIdx.x & 31;
    const int r    = lane >> 2;
    const int q    = lane & 3;
    const float4* xb = (const float4*)(x + (size_t)bt * NF);

    float4 u3[4];
    #pragma unroll
    for (int j = 0; j < 4; j++) u3[j] = ((const float4*)U3)[q + 4*j];

    float4 acc[4];
    #pragma unroll
    for (int j = 0; j < 4; j++) acc[j] = make_float4(0.f,0.f,0.f,0.f);

    const int n0 = w * 256;
    #pragma unroll 2
    for (int k = 0; k < 32; k++) {
        const int n = n0 + 8*k + r;
        const float4* row = xb + (size_t)n * 16;
        const float u1 = __ldg(U1 + n);
        float d = 0.f;
        #pragma unroll
        for (int j = 0; j < 4; j++) {
            float4 v = row[q + 4*j];
            d += v.x*u3[j].x + v.y*u3[j].y + v.z*u3[j].z + v.w*u3[j].w;
            acc[j].x += v.x*u1; acc[j].y += v.y*u1;
            acc[j].z += v.z*u1; acc[j].w += v.w*u1;
        }
        d += __shfl_down_sync(0xffffffffu, d, 2, 4);
        d += __shfl_down_sync(0xffffffffu, d, 1, 4);
        if (q == 0) rhs[bt*NN + n] = d;
    }

    #pragma unroll
    for (int off = 16; off >= 4; off >>= 1) {
        #pragma unroll
        for (int j = 0; j < 4; j++) {
            acc[j].x += __shfl_down_sync(0xffffffffu, acc[j].x, off);
            acc[j].y += __shfl_down_sync(0xffffffffu, acc[j].y, off);
            acc[j].z += __shfl_down_sync(0xffffffffu, acc[j].z, off);
            acc[j].w += __shfl_down_sync(0xffffffffu, acc[j].w, off);
        }
    }

    __shared__ float sred[8][FF];
    if (lane < 4) {
        #pragma unroll
        for (int j = 0; j < 4; j++)
            ((float4*)sred[w])[q + 4*j] = acc[j];
    }
    __syncthreads();
    if (threadIdx.x < FF) {
        float t = 0.f;
        #pragma unroll
        for (int p = 0; p < 8; p++) t += sred[p][threadIdx.x];
        lf[bt*FF + threadIdx.x] = t;
    }
}

// ---------------------------------------------------------------------------
// Kernel 2: G = rhs(384 x 2048) @ U2(2048 x 64), K-split into 8 partials.
// ---------------------------------------------------------------------------
__global__ __launch_bounds__(256) void k2_gemm(
    const float* __restrict__ rhs, const float* __restrict__ U2,
    float* __restrict__ Gp)
{
    __shared__ float Us[64*64];
    __shared__ float Rs[32*65];
    const int m0 = blockIdx.x * 32;
    const int k0 = blockIdx.y * 256;
    const int f  = threadIdx.x & 63;
    const int rg = threadIdx.x >> 6;

    float acc[8];
    #pragma unroll
    for (int r = 0; r < 8; r++) acc[r] = 0.f;

    for (int kc = 0; kc < 256; kc += 64) {
        const int kb = k0 + kc;
        __syncthreads();
        #pragma unroll
        for (int i = 0; i < 16; i++) {
            int e = threadIdx.x + i*256;
            Us[e] = U2[(size_t)(kb + (e>>6))*FF + (e & 63)];
        }
        #pragma unroll
        for (int i = 0; i < 8; i++) {
            int e = threadIdx.x + i*256;
            int row = e >> 6, kk = e & 63;
            Rs[row*65 + kk] = rhs[(size_t)(m0+row)*NN + kb + kk];
        }
        __syncthreads();
        #pragma unroll
        for (int kk = 0; kk < 64; kk++) {
            const float u = Us[kk*64 + f];
            #pragma unroll
            for (int r = 0; r < 8; r++)
                acc[r] += Rs[(rg*8 + r)*65 + kk] * u;
        }
    }
    float* g = Gp + (size_t)blockIdx.y * (BT*FF);
    #pragma unroll
    for (int r = 0; r < 8; r++)
        g[(m0 + rg*8 + r)*FF + f] = acc[r];
}

// ---------------------------------------------------------------------------
// Kernel 3: per batch b: product -> sigmoid(+be) -> E = Ve@sig -> softmax(t).
// ---------------------------------------------------------------------------
__global__ __launch_bounds__(576) void k3_scores(
    const float* __restrict__ lf, const float* __restrict__ Gp,
    const float* __restrict__ be, const float* __restrict__ Ve,
    float* __restrict__ A)
{
    const int b = blockIdx.x;
    __shared__ float lfs[TT*65], Gs[TT*65], sg[TT*25], Em[TT*25];
    __shared__ float cmax[TT], csum[TT];
    const int tid = threadIdx.x;

    for (int e = tid; e < TT*FF; e += 576) {
        int t = e >> 6, f = e & 63;
        lfs[t*65 + f] = lf[(b*TT + t)*FF + f];
        float g = 0.f;
        #pragma unroll
        for (int ks = 0; ks < KSPLIT; ks++)
            g += Gp[(size_t)ks*(BT*FF) + (b*TT + t)*FF + f];
        Gs[t*65 + f] = g;
    }
    __syncthreads();

    const int t = tid / TT;
    const int s = tid % TT;
    float p = 0.f;
    #pragma unroll
    for (int f = 0; f < FF; f++)
        p += lfs[t*65 + f] * Gs[s*65 + f];
    sg[t*25 + s] = 1.f / (1.f + __expf(-(p + be[t*TT + s])));
    __syncthreads();

    float e = 0.f;
    #pragma unroll
    for (int s2 = 0; s2 < TT; s2++)
        e += Ve[t*TT + s2] * sg[s2*25 + s];
    Em[t*25 + s] = e;
    __syncthreads();

    if (t == 0) {
        float m = -1e30f;
        #pragma unroll
        for (int tt2 = 0; tt2 < TT; tt2++) m = fmaxf(m, Em[tt2*25 + s]);
        cmax[s] = m;
    }
    __syncthreads();
    const float ex = __expf(Em[t*25 + s] - cmax[s]);
    Em[t*25 + s] = ex;
    __syncthreads();
    if (t == 0) {
        float sm = 0.f;
        #pragma unroll
        for (int tt2 = 0; tt2 < TT; tt2++) sm += Em[tt2*25 + s];
        csum[s] = sm;
    }
    __syncthreads();
    A[b*TT*TT + t*TT + s] = ex / csum[s];
}

// ---------------------------------------------------------------------------
// Kernel 4: out[b,s,nf] = sum_t x[b,t,nf] * A[b,t,s].
// Each thread owns one float2 column: xr = 24 x float2 (48 regs). A packed as
// float2 pairs over s in smem -> per s-pair: 24 LDS.64 + 96 FFMA.
// ~70 regs -> 3 CTAs/SM (24 warps) for latency hiding. x read once, out
// written once per thread.
// FIX vs R3: A-tile has 288 entries (> 256 threads) -> strided loop load.
// ---------------------------------------------------------------------------
__global__ __launch_bounds__(256, 3) void k4_out(
    const float2* __restrict__ x2, const float* __restrict__ A,
    float2* __restrict__ out2)
{
    __shared__ float2 As2[TT*12];   // [t][sp] = (A[t,2sp], A[t,2sp+1])
    const int b = blockIdx.y;
    for (int i = threadIdx.x; i < TT*12; i += 256) {
        const int t  = i / 12;
        const int sp = i % 12;
        As2[i] = make_float2(A[b*TT*TT + t*TT + 2*sp],
                             A[b*TT*TT + t*TT + 2*sp + 1]);
    }
    __syncthreads();

    const size_t c = (size_t)blockIdx.x * 256 + threadIdx.x;  // float2 column
    const float2* xb = x2 + (size_t)b * TT * NF2 + c;

    float2 xr[TT];
    #pragma unroll
    for (int t = 0; t < TT; t++) xr[t] = xb[(size_t)t * NF2];

    float2* ob = out2 + (size_t)b * TT * NF2 + c;
    #pragma unroll 2
    for (int sp = 0; sp < 12; sp++) {
        float2 a0 = make_float2(0.f, 0.f);
        float2 a1 = make_float2(0.f, 0.f);
        #pragma unroll
        for (int t = 0; t < TT; t++) {
            const float2 av = As2[t*12 + sp];
            a0.x += xr[t].x * av.x;  a0.y += xr[t].y * av.x;
            a1.x += xr[t].x * av.y;  a1.y += xr[t].y * av.y;
        }
        ob[(size_t)(2*sp)     * NF2] = a0;
        ob[(size_t)(2*sp + 1) * NF2] = a1;
    }
}

// ---------------------------------------------------------------------------
extern "C" void kernel_launch(void* const* d_in, const int* in_sizes, int n_in,
                              void* d_out, int out_size)
{
    const float* x  = (const float*)d_in[0];  // (16,24,2048,64)
    const float* U1 = (const float*)d_in[1];  // (2048)
    const float* U2 = (const float*)d_in[2];  // (2048,64)
    const float* U3 = (const float*)d_in[3];  // (64)
    const float* be = (const float*)d_in[4];  // (24,24)
    const float* Ve = (const float*)d_in[5];  // (24,24)

    float *rhs, *lf, *Gp, *A;
    cudaGetSymbolAddress((void**)&rhs, d_rhs);
    cudaGetSymbolAddress((void**)&lf,  d_lf);
    cudaGetSymbolAddress((void**)&Gp,  d_Gp);
    cudaGetSymbolAddress((void**)&A,   d_A);

    k1_pass<<<BT, 256>>>(x, U1, U3, rhs, lf);
    k2_gemm<<<dim3(BT/32, KSPLIT), 256>>>(rhs, U2, Gp);
    k3_scores<<<BB, 576>>>(lf, Gp, be, Ve, A);
    k4_out<<<dim3(NF2/256, BB), 256>>>((const float2*)x, A, (float2*)d_out);
}

// round 5
// speedup vs baseline: 1.9758x; 1.9758x over previous
#include <cuda_runtime.h>
#include <cuda_bf16.h>

// Problem constants
#define BB 16
#define TT 24
#define NN 2048
#define FF 64
#define BT (BB*TT)          // 384
#define NF (NN*FF)          // 131072
#define NF4 (NF/4)          // 32768 float4 per (b,t) row
#define KSPLIT 8

// Scratch (device globals; no allocation allowed). All fully overwritten each call.
__device__ float d_rhs[BT*NN];        // 3 MB
__device__ float d_lf [BT*FF];        // lhs_f
__device__ float d_Gp [KSPLIT*BT*FF]; // K-split partials of G
__device__ float d_A  [BB*TT*TT];     // attention weights

// ---------------------------------------------------------------------------
// Kernel 1: one pass over x per (b,t) block.
//   rhs[n]   = sum_f x[n,f]*U3[f]
//   lhs_f[f] = sum_n x[n,f]*U1[n]
// ---------------------------------------------------------------------------
__global__ __launch_bounds__(256) void k1_pass(
    const float* __restrict__ x, const float* __restrict__ U1,
    const float* __restrict__ U3, float* __restrict__ rhs, float* __restrict__ lf)
{
    const int bt   = blockIdx.x;
    const int w    = threadIdx.x >> 5;
    const int lane = threadIdx.x & 31;
    const int r    = lane >> 2;
    const int q    = lane & 3;
    const float4* xb = (const float4*)(x + (size_t)bt * NF);

    float4 u3[4];
    #pragma unroll
    for (int j = 0; j < 4; j++) u3[j] = ((const float4*)U3)[q + 4*j];

    float4 acc[4];
    #pragma unroll
    for (int j = 0; j < 4; j++) acc[j] = make_float4(0.f,0.f,0.f,0.f);

    const int n0 = w * 256;
    #pragma unroll 2
    for (int k = 0; k < 32; k++) {
        const int n = n0 + 8*k + r;
        const float4* row = xb + (size_t)n * 16;
        const float u1 = __ldg(U1 + n);
        float d = 0.f;
        #pragma unroll
        for (int j = 0; j < 4; j++) {
            float4 v = row[q + 4*j];
            d += v.x*u3[j].x + v.y*u3[j].y + v.z*u3[j].z + v.w*u3[j].w;
            acc[j].x += v.x*u1; acc[j].y += v.y*u1;
            acc[j].z += v.z*u1; acc[j].w += v.w*u1;
        }
        d += __shfl_down_sync(0xffffffffu, d, 2, 4);
        d += __shfl_down_sync(0xffffffffu, d, 1, 4);
        if (q == 0) rhs[bt*NN + n] = d;
    }

    #pragma unroll
    for (int off = 16; off >= 4; off >>= 1) {
        #pragma unroll
        for (int j = 0; j < 4; j++) {
            acc[j].x += __shfl_down_sync(0xffffffffu, acc[j].x, off);
            acc[j].y += __shfl_down_sync(0xffffffffu, acc[j].y, off);
            acc[j].z += __shfl_down_sync(0xffffffffu, acc[j].z, off);
            acc[j].w += __shfl_down_sync(0xffffffffu, acc[j].w, off);
        }
    }

    __shared__ float sred[8][FF];
    if (lane < 4) {
        #pragma unroll
        for (int j = 0; j < 4; j++)
            ((float4*)sred[w])[q + 4*j] = acc[j];
    }
    __syncthreads();
    if (threadIdx.x < FF) {
        float t = 0.f;
        #pragma unroll
        for (int p = 0; p < 8; p++) t += sred[p][threadIdx.x];
        lf[bt*FF + threadIdx.x] = t;
    }
}

// ---------------------------------------------------------------------------
// Kernel 2: G = rhs(384 x 2048) @ U2(2048 x 64), K-split into 8 partials.
// ---------------------------------------------------------------------------
__global__ __launch_bounds__(256) void k2_gemm(
    const float* __restrict__ rhs, const float* __restrict__ U2,
    float* __restrict__ Gp)
{
    __shared__ float Us[64*64];
    __shared__ float Rs[32*65];
    const int m0 = blockIdx.x * 32;
    const int k0 = blockIdx.y * 256;
    const int f  = threadIdx.x & 63;
    const int rg = threadIdx.x >> 6;

    float acc[8];
    #pragma unroll
    for (int r = 0; r < 8; r++) acc[r] = 0.f;

    for (int kc = 0; kc < 256; kc += 64) {
        const int kb = k0 + kc;
        __syncthreads();
        #pragma unroll
        for (int i = 0; i < 16; i++) {
            int e = threadIdx.x + i*256;
            Us[e] = U2[(size_t)(kb + (e>>6))*FF + (e & 63)];
        }
        #pragma unroll
        for (int i = 0; i < 8; i++) {
            int e = threadIdx.x + i*256;
            int row = e >> 6, kk = e & 63;
            Rs[row*65 + kk] = rhs[(size_t)(m0+row)*NN + kb + kk];
        }
        __syncthreads();
        #pragma unroll
        for (int kk = 0; kk < 64; kk++) {
            const float u = Us[kk*64 + f];
            #pragma unroll
            for (int r = 0; r < 8; r++)
                acc[r] += Rs[(rg*8 + r)*65 + kk] * u;
        }
    }
    float* g = Gp + (size_t)blockIdx.y * (BT*FF);
    #pragma unroll
    for (int r = 0; r < 8; r++)
        g[(m0 + rg*8 + r)*FF + f] = acc[r];
}

// ---------------------------------------------------------------------------
// Kernel 3: per batch b: product -> sigmoid(+be) -> E = Ve@sig -> softmax(t).
// ---------------------------------------------------------------------------
__global__ __launch_bounds__(576) void k3_scores(
    const float* __restrict__ lf, const float* __restrict__ Gp,
    const float* __restrict__ be, const float* __restrict__ Ve,
    float* __restrict__ A)
{
    const int b = blockIdx.x;
    __shared__ float lfs[TT*65], Gs[TT*65], sg[TT*25], Em[TT*25];
    __shared__ float cmax[TT], csum[TT];
    const int tid = threadIdx.x;

    for (int e = tid; e < TT*FF; e += 576) {
        int t = e >> 6, f = e & 63;
        lfs[t*65 + f] = lf[(b*TT + t)*FF + f];
        float g = 0.f;
        #pragma unroll
        for (int ks = 0; ks < KSPLIT; ks++)
            g += Gp[(size_t)ks*(BT*FF) + (b*TT + t)*FF + f];
        Gs[t*65 + f] = g;
    }
    __syncthreads();

    const int t = tid / TT;
    const int s = tid % TT;
    float p = 0.f;
    #pragma unroll
    for (int f = 0; f < FF; f++)
        p += lfs[t*65 + f] * Gs[s*65 + f];
    sg[t*25 + s] = 1.f / (1.f + __expf(-(p + be[t*TT + s])));
    __syncthreads();

    float e = 0.f;
    #pragma unroll
    for (int s2 = 0; s2 < TT; s2++)
        e += Ve[t*TT + s2] * sg[s2*25 + s];
    Em[t*25 + s] = e;
    __syncthreads();

    if (t == 0) {
        float m = -1e30f;
        #pragma unroll
        for (int tt2 = 0; tt2 < TT; tt2++) m = fmaxf(m, Em[tt2*25 + s]);
        cmax[s] = m;
    }
    __syncthreads();
    const float ex = __expf(Em[t*25 + s] - cmax[s]);
    Em[t*25 + s] = ex;
    __syncthreads();
    if (t == 0) {
        float sm = 0.f;
        #pragma unroll
        for (int tt2 = 0; tt2 < TT; tt2++) sm += Em[tt2*25 + s];
        csum[s] = sm;
    }
    __syncthreads();
    A[b*TT*TT + t*TT + s] = ex / csum[s];
}

// ---------------------------------------------------------------------------
// Kernel 4: out[b,s,nf] = sum_t x[b,t,nf] * A[b,t,s].
// Each thread owns one float4 column (xr = 24 x float4 = 96 regs; x read once,
// out written once). A staged in smem as float4 over s-groups of 4:
// inner loop = 1 LDS.128 broadcast + 16 FFMA. 128-thread CTAs, 3 CTAs/SM
// (reg cap 170 -> no spills) = 12 warps/SM.
// ---------------------------------------------------------------------------
__global__ __launch_bounds__(128, 3) void k4_out(
    const float4* __restrict__ x4, const float* __restrict__ A,
    float4* __restrict__ out4)
{
    __shared__ float4 As4[TT*6];   // [t][sg] = A[t, 4sg..4sg+3]
    const int b = blockIdx.y;
    const float4* Ab4 = (const float4*)(A + b*TT*TT);
    for (int i = threadIdx.x; i < TT*6; i += 128)
        As4[i] = Ab4[i];
    __syncthreads();

    const size_t c = (size_t)blockIdx.x * 128 + threadIdx.x;  // float4 column
    const float4* xb = x4 + (size_t)b * TT * NF4 + c;

    float4 xr[TT];
    #pragma unroll
    for (int t = 0; t < TT; t++) xr[t] = xb[(size_t)t * NF4];

    float4* ob = out4 + (size_t)b * TT * NF4 + c;
    #pragma unroll 1
    for (int sg = 0; sg < 6; sg++) {
        float4 a0 = make_float4(0.f,0.f,0.f,0.f);
        float4 a1 = make_float4(0.f,0.f,0.f,0.f);
        float4 a2 = make_float4(0.f,0.f,0.f,0.f);
        float4 a3 = make_float4(0.f,0.f,0.f,0.f);
        #pragma unroll
        for (int t = 0; t < TT; t++) {
            const float4 av = As4[t*6 + sg];
            a0.x += xr[t].x*av.x; a0.y += xr[t].y*av.x; a0.z += xr[t].z*av.x; a0.w += xr[t].w*av.x;
            a1.x += xr[t].x*av.y; a1.y += xr[t].y*av.y; a1.z += xr[t].z*av.y; a1.w += xr[t].w*av.y;
            a2.x += xr[t].x*av.z; a2.y += xr[t].y*av.z; a2.z += xr[t].z*av.z; a2.w += xr[t].w*av.z;
            a3.x += xr[t].x*av.w; a3.y += xr[t].y*av.w; a3.z += xr[t].z*av.w; a3.w += xr[t].w*av.w;
        }
        ob[(size_t)(4*sg + 0) * NF4] = a0;
        ob[(size_t)(4*sg + 1) * NF4] = a1;
        ob[(size_t)(4*sg + 2) * NF4] = a2;
        ob[(size_t)(4*sg + 3) * NF4] = a3;
    }
}

// ---------------------------------------------------------------------------
extern "C" void kernel_launch(void* const* d_in, const int* in_sizes, int n_in,
                              void* d_out, int out_size)
{
    const float* x  = (const float*)d_in[0];  // (16,24,2048,64)
    const float* U1 = (const float*)d_in[1];  // (2048)
    const float* U2 = (const float*)d_in[2];  // (2048,64)
    const float* U3 = (const float*)d_in[3];  // (64)
    const float* be = (const float*)d_in[4];  // (24,24)
    const float* Ve = (const float*)d_in[5];  // (24,24)

    float *rhs, *lf, *Gp, *A;
    cudaGetSymbolAddress((void**)&rhs, d_rhs);
    cudaGetSymbolAddress((void**)&lf,  d_lf);
    cudaGetSymbolAddress((void**)&Gp,  d_Gp);
    cudaGetSymbolAddress((void**)&A,   d_A);

    k1_pass<<<BT, 256>>>(x, U1, U3, rhs, lf);
    k2_gemm<<<dim3(BT/32, KSPLIT), 256>>>(rhs, U2, Gp);
    k3_scores<<<BB, 576>>>(lf, Gp, be, Ve, A);
    k4_out<<<dim3(NF4/128, BB), 128>>>((const float4*)x, A, (float4*)d_out);
}

// round 6
// speedup vs baseline: 2.0449x; 1.0350x over previous
#include <cuda_runtime.h>
#include <cuda_bf16.h>

// Problem constants
#define BB 16
#define TT 24
#define NN 2048
#define FF 64
#define BT (BB*TT)          // 384
#define NF (NN*FF)          // 131072
#define NF4 (NF/4)          // 32768 float4 per (b,t) row
#define KSPLIT 8

// Scratch (device globals; no allocation allowed). All fully overwritten each call.
__device__ float d_rhs[BT*NN];         // 3 MB
__device__ float d_lfp[2*BT*FF];       // lhs_f partials (2 halves per bt)
__device__ float d_Gp [KSPLIT*BT*FF];  // K-split partials of G
__device__ float d_A  [BB*TT*TT];      // attention weights

// ---------------------------------------------------------------------------
// Kernel 1: pass over x. Each CTA (128 thr) handles half the n-range of one
// (b,t): grid = 768 for load balance (768/148 = 5.2). Per warp: 256 rows,
// 8 rows/iter (4 lanes/row), unroll 4 -> 16 LDG.128 in flight.
//   rhs[n]   = sum_f x[n,f]*U3[f]
//   lfp[cta][f] partial of sum_n x[n,f]*U1[n]  (k3 sums the two halves)
// ---------------------------------------------------------------------------
__global__ __launch_bounds__(128) void k1_pass(
    const float* __restrict__ x, const float* __restrict__ U1,
    const float* __restrict__ U3, float* __restrict__ rhs, float* __restrict__ lfp)
{
    const int bt   = blockIdx.x >> 1;
    const int half = blockIdx.x & 1;
    const int w    = threadIdx.x >> 5;
    const int lane = threadIdx.x & 31;
    const int r    = lane >> 2;
    const int q    = lane & 3;
    const float4* xb = (const float4*)(x + (size_t)bt * NF);

    float4 u3[4];
    #pragma unroll
    for (int j = 0; j < 4; j++) u3[j] = ((const float4*)U3)[q + 4*j];

    float4 acc[4];
    #pragma unroll
    for (int j = 0; j < 4; j++) acc[j] = make_float4(0.f,0.f,0.f,0.f);

    const int n0 = half * 1024 + w * 256;
    #pragma unroll 4
    for (int k = 0; k < 32; k++) {
        const int n = n0 + 8*k + r;
        const float4* row = xb + (size_t)n * 16;
        const float u1 = __ldg(U1 + n);
        float d = 0.f;
        #pragma unroll
        for (int j = 0; j < 4; j++) {
            float4 v = row[q + 4*j];
            d += v.x*u3[j].x + v.y*u3[j].y + v.z*u3[j].z + v.w*u3[j].w;
            acc[j].x += v.x*u1; acc[j].y += v.y*u1;
            acc[j].z += v.z*u1; acc[j].w += v.w*u1;
        }
        d += __shfl_down_sync(0xffffffffu, d, 2, 4);
        d += __shfl_down_sync(0xffffffffu, d, 1, 4);
        if (q == 0) rhs[bt*NN + n] = d;
    }

    #pragma unroll
    for (int off = 16; off >= 4; off >>= 1) {
        #pragma unroll
        for (int j = 0; j < 4; j++) {
            acc[j].x += __shfl_down_sync(0xffffffffu, acc[j].x, off);
            acc[j].y += __shfl_down_sync(0xffffffffu, acc[j].y, off);
            acc[j].z += __shfl_down_sync(0xffffffffu, acc[j].z, off);
            acc[j].w += __shfl_down_sync(0xffffffffu, acc[j].w, off);
        }
    }

    __shared__ float sred[4][FF];
    if (lane < 4) {
        #pragma unroll
        for (int j = 0; j < 4; j++)
            ((float4*)sred[w])[q + 4*j] = acc[j];
    }
    __syncthreads();
    if (threadIdx.x < FF) {
        float t = 0.f;
        #pragma unroll
        for (int p = 0; p < 4; p++) t += sred[p][threadIdx.x];
        lfp[blockIdx.x*FF + threadIdx.x] = t;
    }
}

// ---------------------------------------------------------------------------
// Kernel 2: G = rhs(384 x 2048) @ U2(2048 x 64), K-split into 8 partials.
// ---------------------------------------------------------------------------
__global__ __launch_bounds__(256) void k2_gemm(
    const float* __restrict__ rhs, const float* __restrict__ U2,
    float* __restrict__ Gp)
{
    __shared__ float Us[64*64];
    __shared__ float Rs[32*65];
    const int m0 = blockIdx.x * 32;
    const int k0 = blockIdx.y * 256;
    const int f  = threadIdx.x & 63;
    const int rg = threadIdx.x >> 6;

    float acc[8];
    #pragma unroll
    for (int r = 0; r < 8; r++) acc[r] = 0.f;

    for (int kc = 0; kc < 256; kc += 64) {
        const int kb = k0 + kc;
        __syncthreads();
        #pragma unroll
        for (int i = 0; i < 16; i++) {
            int e = threadIdx.x + i*256;
            Us[e] = U2[(size_t)(kb + (e>>6))*FF + (e & 63)];
        }
        #pragma unroll
        for (int i = 0; i < 8; i++) {
            int e = threadIdx.x + i*256;
            int row = e >> 6, kk = e & 63;
            Rs[row*65 + kk] = rhs[(size_t)(m0+row)*NN + kb + kk];
        }
        __syncthreads();
        #pragma unroll
        for (int kk = 0; kk < 64; kk++) {
            const float u = Us[kk*64 + f];
            #pragma unroll
            for (int r = 0; r < 8; r++)
                acc[r] += Rs[(rg*8 + r)*65 + kk] * u;
        }
    }
    float* g = Gp + (size_t)blockIdx.y * (BT*FF);
    #pragma unroll
    for (int r = 0; r < 8; r++)
        g[(m0 + rg*8 + r)*FF + f] = acc[r];
}

// ---------------------------------------------------------------------------
// Kernel 3: per batch b: product -> sigmoid(+be) -> E = Ve@sig -> softmax(t).
// ---------------------------------------------------------------------------
__global__ __launch_bounds__(576) void k3_scores(
    const float* __restrict__ lfp, const float* __restrict__ Gp,
    const float* __restrict__ be, const float* __restrict__ Ve,
    float* __restrict__ A)
{
    const int b = blockIdx.x;
    __shared__ float lfs[TT*65], Gs[TT*65], sg[TT*25], Em[TT*25];
    __shared__ float cmax[TT], csum[TT];
    const int tid = threadIdx.x;

    for (int e = tid; e < TT*FF; e += 576) {
        int t = e >> 6, f = e & 63;
        const int bt = b*TT + t;
        lfs[t*65 + f] = lfp[(bt*2    )*FF + f] + lfp[(bt*2 + 1)*FF + f];
        float g = 0.f;
        #pragma unroll
        for (int ks = 0; ks < KSPLIT; ks++)
            g += Gp[(size_t)ks*(BT*FF) + bt*FF + f];
        Gs[t*65 + f] = g;
    }
    __syncthreads();

    const int t = tid / TT;
    const int s = tid % TT;
    float p = 0.f;
    #pragma unroll
    for (int f = 0; f < FF; f++)
        p += lfs[t*65 + f] * Gs[s*65 + f];
    sg[t*25 + s] = 1.f / (1.f + __expf(-(p + be[t*TT + s])));
    __syncthreads();

    float e = 0.f;
    #pragma unroll
    for (int s2 = 0; s2 < TT; s2++)
        e += Ve[t*TT + s2] * sg[s2*25 + s];
    Em[t*25 + s] = e;
    __syncthreads();

    if (t == 0) {
        float m = -1e30f;
        #pragma unroll
        for (int tt2 = 0; tt2 < TT; tt2++) m = fmaxf(m, Em[tt2*25 + s]);
        cmax[s] = m;
    }
    __syncthreads();
    const float ex = __expf(Em[t*25 + s] - cmax[s]);
    Em[t*25 + s] = ex;
    __syncthreads();
    if (t == 0) {
        float sm = 0.f;
        #pragma unroll
        for (int tt2 = 0; tt2 < TT; tt2++) sm += Em[tt2*25 + s];
        csum[s] = sm;
    }
    __syncthreads();
    A[b*TT*TT + t*TT + s] = ex / csum[s];
}

// ---------------------------------------------------------------------------
// Kernel 4: out[b,s,nf] = sum_t x[b,t,nf] * A[b,t,s].
// Each thread owns one float4 column (xr = 24 x float4). s processed in PAIRS
// (a0,a1 only -> ~120 live regs) with A staged as float2 -> fits 4 CTAs/SM
// (16 warps) under __launch_bounds__(128,4). Batches processed in REVERSE so
// the first waves hit x still resident in L2 from k1.
// ---------------------------------------------------------------------------
__global__ __launch_bounds__(128, 4) void k4_out(
    const float4* __restrict__ x4, const float* __restrict__ A,
    float4* __restrict__ out4)
{
    __shared__ float2 As2[TT*12];   // [t][sp] = (A[t,2sp], A[t,2sp+1])
    const int b = (BB - 1) - blockIdx.y;   // reverse batch order for L2 reuse
    const float2* Ab2 = (const float2*)(A + b*TT*TT);
    for (int i = threadIdx.x; i < TT*12; i += 128)
        As2[i] = Ab2[i];
    __syncthreads();

    const size_t c = (size_t)blockIdx.x * 128 + threadIdx.x;  // float4 column
    const float4* xb = x4 + (size_t)b * TT * NF4 + c;

    float4 xr[TT];
    #pragma unroll
    for (int t = 0; t < TT; t++) xr[t] = xb[(size_t)t * NF4];

    float4* ob = out4 + (size_t)b * TT * NF4 + c;
    #pragma unroll 1
    for (int sp = 0; sp < 12; sp++) {
        float4 a0 = make_float4(0.f,0.f,0.f,0.f);
        float4 a1 = make_float4(0.f,0.f,0.f,0.f);
        #pragma unroll
        for (int t = 0; t < TT; t++) {
            const float2 av = As2[t*12 + sp];
            a0.x += xr[t].x*av.x; a0.y += xr[t].y*av.x; a0.z += xr[t].z*av.x; a0.w += xr[t].w*av.x;
            a1.x += xr[t].x*av.y; a1.y += xr[t].y*av.y; a1.z += xr[t].z*av.y; a1.w += xr[t].w*av.y;
        }
        ob[(size_t)(2*sp    ) * NF4] = a0;
        ob[(size_t)(2*sp + 1) * NF4] = a1;
    }
}

// ---------------------------------------------------------------------------
extern "C" void kernel_launch(void* const* d_in, const int* in_sizes, int n_in,
                              void* d_out, int out_size)
{
    const float* x  = (const float*)d_in[0];  // (16,24,2048,64)
    const float* U1 = (const float*)d_in[1];  // (2048)
    const float* U2 = (const float*)d_in[2];  // (2048,64)
    const float* U3 = (const float*)d_in[3];  // (64)
    const float* be = (const float*)d_in[4];  // (24,24)
    const float* Ve = (const float*)d_in[5];  // (24,24)

    float *rhs, *lfp, *Gp, *A;
    cudaGetSymbolAddress((void**)&rhs, d_rhs);
    cudaGetSymbolAddress((void**)&lfp, d_lfp);
    cudaGetSymbolAddress((void**)&Gp,  d_Gp);
    cudaGetSymbolAddress((void**)&A,   d_A);

    k1_pass<<<BT*2, 128>>>(x, U1, U3, rhs, lfp);
    k2_gemm<<<dim3(BT/32, KSPLIT), 256>>>(rhs, U2, Gp);
    k3_scores<<<BB, 576>>>(lfp, Gp, be, Ve, A);
    k4_out<<<dim3(NF4/128, BB), 128>>>((const float4*)x, A, (float4*)d_out);
}

// round 7
// speedup vs baseline: 2.1134x; 1.0335x over previous
#include <cuda_runtime.h>
#include <cuda_bf16.h>

// Problem constants
#define BB 16
#define TT 24
#define NN 2048
#define FF 64
#define BT (BB*TT)          // 384
#define NF (NN*FF)          // 131072
#define NF4 (NF/4)          // 32768 float4 per (b,t) row
#define KSPLIT 16

// Scratch (device globals; no allocation allowed). All fully overwritten each call.
__device__ float d_rhs[BT*NN];         // 3 MB
__device__ float d_lfp[2*BT*FF];       // lhs_f partials (2 halves per bt)
__device__ float d_Gp [KSPLIT*BT*FF];  // K-split partials of G (1.5 MB)
__device__ float d_A  [BB*TT*TT];      // attention weights

// ---------------------------------------------------------------------------
// Kernel 1: pass over x. Each CTA (128 thr) handles half the n-range of one
// (b,t): grid = 768. Per warp: 256 rows, 8 rows/iter (4 lanes/row), unroll 4.
//   rhs[n]   = sum_f x[n,f]*U3[f]
//   lfp[cta][f] partial of sum_n x[n,f]*U1[n]  (k3 sums the two halves)
// ---------------------------------------------------------------------------
__global__ __launch_bounds__(128) void k1_pass(
    const float* __restrict__ x, const float* __restrict__ U1,
    const float* __restrict__ U3, float* __restrict__ rhs, float* __restrict__ lfp)
{
    const int bt   = blockIdx.x >> 1;
    const int half = blockIdx.x & 1;
    const int w    = threadIdx.x >> 5;
    const int lane = threadIdx.x & 31;
    const int r    = lane >> 2;
    const int q    = lane & 3;
    const float4* xb = (const float4*)(x + (size_t)bt * NF);

    float4 u3[4];
    #pragma unroll
    for (int j = 0; j < 4; j++) u3[j] = ((const float4*)U3)[q + 4*j];

    float4 acc[4];
    #pragma unroll
    for (int j = 0; j < 4; j++) acc[j] = make_float4(0.f,0.f,0.f,0.f);

    const int n0 = half * 1024 + w * 256;
    #pragma unroll 4
    for (int k = 0; k < 32; k++) {
        const int n = n0 + 8*k + r;
        const float4* row = xb + (size_t)n * 16;
        const float u1 = __ldg(U1 + n);
        float d = 0.f;
        #pragma unroll
        for (int j = 0; j < 4; j++) {
            float4 v = row[q + 4*j];
            d += v.x*u3[j].x + v.y*u3[j].y + v.z*u3[j].z + v.w*u3[j].w;
            acc[j].x += v.x*u1; acc[j].y += v.y*u1;
            acc[j].z += v.z*u1; acc[j].w += v.w*u1;
        }
        d += __shfl_down_sync(0xffffffffu, d, 2, 4);
        d += __shfl_down_sync(0xffffffffu, d, 1, 4);
        if (q == 0) rhs[bt*NN + n] = d;
    }

    #pragma unroll
    for (int off = 16; off >= 4; off >>= 1) {
        #pragma unroll
        for (int j = 0; j < 4; j++) {
            acc[j].x += __shfl_down_sync(0xffffffffu, acc[j].x, off);
            acc[j].y += __shfl_down_sync(0xffffffffu, acc[j].y, off);
            acc[j].z += __shfl_down_sync(0xffffffffu, acc[j].z, off);
            acc[j].w += __shfl_down_sync(0xffffffffu, acc[j].w, off);
        }
    }

    __shared__ float sred[4][FF];
    if (lane < 4) {
        #pragma unroll
        for (int j = 0; j < 4; j++)
            ((float4*)sred[w])[q + 4*j] = acc[j];
    }
    __syncthreads();
    if (threadIdx.x < FF) {
        float t = 0.f;
        #pragma unroll
        for (int p = 0; p < 4; p++) t += sred[p][threadIdx.x];
        lfp[blockIdx.x*FF + threadIdx.x] = t;
    }
}

// ---------------------------------------------------------------------------
// Kernel 2: G = rhs(384 x 2048) @ U2(2048 x 64), K-split into 16 partials.
// 128 threads, tile 32 rows x 64 cols. Thread = 4 rows x 4 cols (acc 4xfloat4):
// inner loop per kk = 1 LDS.128 (U) + 4 broadcast LDS.32 (R) + 16 FFMA.
// grid = (12, 16) = 192 CTAs -> fills all SMs.
// ---------------------------------------------------------------------------
__global__ __launch_bounds__(128) void k2_gemm(
    const float* __restrict__ rhs, const float* __restrict__ U2,
    float* __restrict__ Gp)
{
    __shared__ float4 Us4[64*16];   // [kk][c4], 16 KB
    __shared__ float  Rs [32*68];   // [row][kk], pad 68 (16B-aligned rows), 8.7 KB
    const int m0 = blockIdx.x * 32;
    const int k0 = blockIdx.y * 128;     // 128 K per CTA
    const int c4 = threadIdx.x & 15;     // 4 cols: f = c4*4
    const int rg = threadIdx.x >> 4;     // 8 groups of 4 rows

    float4 acc[4];
    #pragma unroll
    for (int r = 0; r < 4; r++) acc[r] = make_float4(0.f,0.f,0.f,0.f);

    for (int kc = 0; kc < 128; kc += 64) {
        const int kb = k0 + kc;
        __syncthreads();
        // stage U2 rows kb..kb+63 (1024 float4, 8 per thread)
        #pragma unroll
        for (int i = 0; i < 8; i++) {
            int e = threadIdx.x + i*128;
            int kk = e >> 4, cc = e & 15;
            Us4[e] = ((const float4*)(U2 + (size_t)(kb + kk)*FF))[cc];
        }
        // stage rhs rows m0..m0+31, cols kb..kb+63 (512 float4, 4 per thread)
        #pragma unroll
        for (int i = 0; i < 4; i++) {
            int e = threadIdx.x + i*128;
            int row = e >> 4, kq = e & 15;
            float4 v = *(const float4*)(rhs + (size_t)(m0 + row)*NN + kb + kq*4);
            *(float4*)&Rs[row*68 + kq*4] = v;
        }
        __syncthreads();
        #pragma unroll
        for (int kk = 0; kk < 64; kk++) {
            const float4 u = Us4[kk*16 + c4];
            #pragma unroll
            for (int r = 0; r < 4; r++) {
                const float rv = Rs[(rg*4 + r)*68 + kk];
                acc[r].x += rv*u.x; acc[r].y += rv*u.y;
                acc[r].z += rv*u.z; acc[r].w += rv*u.w;
            }
        }
    }
    float* g = Gp + (size_t)blockIdx.y * (BT*FF);
    #pragma unroll
    for (int r = 0; r < 4; r++)
        *(float4*)&g[(m0 + rg*4 + r)*FF + c4*4] = acc[r];
}

// ---------------------------------------------------------------------------
// Kernel 3: per batch b: product -> sigmoid(+be) -> E = Ve@sig -> softmax(t).
// ---------------------------------------------------------------------------
__global__ __launch_bounds__(576) void k3_scores(
    const float* __restrict__ lfp, const float* __restrict__ Gp,
    const float* __restrict__ be, const float* __restrict__ Ve,
    float* __restrict__ A)
{
    const int b = blockIdx.x;
    __shared__ float lfs[TT*65], Gs[TT*65], sg[TT*25], Em[TT*25];
    __shared__ float cmax[TT], csum[TT];
    const int tid = threadIdx.x;

    for (int e = tid; e < TT*FF; e += 576) {
        int t = e >> 6, f = e & 63;
        const int bt = b*TT + t;
        lfs[t*65 + f] = lfp[(bt*2    )*FF + f] + lfp[(bt*2 + 1)*FF + f];
        float g = 0.f;
        #pragma unroll
        for (int ks = 0; ks < KSPLIT; ks++)
            g += Gp[(size_t)ks*(BT*FF) + bt*FF + f];
        Gs[t*65 + f] = g;
    }
    __syncthreads();

    const int t = tid / TT;
    const int s = tid % TT;
    float p = 0.f;
    #pragma unroll
    for (int f = 0; f < FF; f++)
        p += lfs[t*65 + f] * Gs[s*65 + f];
    sg[t*25 + s] = 1.f / (1.f + __expf(-(p + be[t*TT + s])));
    __syncthreads();

    float e = 0.f;
    #pragma unroll
    for (int s2 = 0; s2 < TT; s2++)
        e += Ve[t*TT + s2] * sg[s2*25 + s];
    Em[t*25 + s] = e;
    __syncthreads();

    if (t == 0) {
        float m = -1e30f;
        #pragma unroll
        for (int tt2 = 0; tt2 < TT; tt2++) m = fmaxf(m, Em[tt2*25 + s]);
        cmax[s] = m;
    }
    __syncthreads();
    const float ex = __expf(Em[t*25 + s] - cmax[s]);
    Em[t*25 + s] = ex;
    __syncthreads();
    if (t == 0) {
        float sm = 0.f;
        #pragma unroll
        for (int tt2 = 0; tt2 < TT; tt2++) sm += Em[tt2*25 + s];
        csum[s] = sm;
    }
    __syncthreads();
    A[b*TT*TT + t*TT + s] = ex / csum[s];
}

// ---------------------------------------------------------------------------
// Kernel 4: out[b,s,nf] = sum_t x[b,t,nf] * A[b,t,s].
// float4 column per thread (xr = 24 x float4), s in pairs, A as float2 in smem,
// 4 CTAs/SM. Reverse batch order for L2 reuse of k1's tail.
// ---------------------------------------------------------------------------
__global__ __launch_bounds__(128, 4) void k4_out(
    const float4* __restrict__ x4, const float* __restrict__ A,
    float4* __restrict__ out4)
{
    __shared__ float2 As2[TT*12];   // [t][sp] = (A[t,2sp], A[t,2sp+1])
    const int b = (BB - 1) - blockIdx.y;   // reverse batch order for L2 reuse
    const float2* Ab2 = (const float2*)(A + b*TT*TT);
    for (int i = threadIdx.x; i < TT*12; i += 128)
        As2[i] = Ab2[i];
    __syncthreads();

    const size_t c = (size_t)blockIdx.x * 128 + threadIdx.x;  // float4 column
    const float4* xb = x4 + (size_t)b * TT * NF4 + c;

    float4 xr[TT];
    #pragma unroll
    for (int t = 0; t < TT; t++) xr[t] = xb[(size_t)t * NF4];

    float4* ob = out4 + (size_t)b * TT * NF4 + c;
    #pragma unroll 1
    for (int sp = 0; sp < 12; sp++) {
        float4 a0 = make_float4(0.f,0.f,0.f,0.f);
        float4 a1 = make_float4(0.f,0.f,0.f,0.f);
        #pragma unroll
        for (int t = 0; t < TT; t++) {
            const float2 av = As2[t*12 + sp];
            a0.x += xr[t].x*av.x; a0.y += xr[t].y*av.x; a0.z += xr[t].z*av.x; a0.w += xr[t].w*av.x;
            a1.x += xr[t].x*av.y; a1.y += xr[t].y*av.y; a1.z += xr[t].z*av.y; a1.w += xr[t].w*av.y;
        }
        ob[(size_t)(2*sp    ) * NF4] = a0;
        ob[(size_t)(2*sp + 1) * NF4] = a1;
    }
}

// ---------------------------------------------------------------------------
extern "C" void kernel_launch(void* const* d_in, const int* in_sizes, int n_in,
                              void* d_out, int out_size)
{
    const float* x  = (const float*)d_in[0];  // (16,24,2048,64)
    const float* U1 = (const float*)d_in[1];  // (2048)
    const float* U2 = (const float*)d_in[2];  // (2048,64)
    const float* U3 = (const float*)d_in[3];  // (64)
    const float* be = (const float*)d_in[4];  // (24,24)
    const float* Ve = (const float*)d_in[5];  // (24,24)

    float *rhs, *lfp, *Gp, *A;
    cudaGetSymbolAddress((void**)&rhs, d_rhs);
    cudaGetSymbolAddress((void**)&lfp, d_lfp);
    cudaGetSymbolAddress((void**)&Gp,  d_Gp);
    cudaGetSymbolAddress((void**)&A,   d_A);

    k1_pass<<<BT*2, 128>>>(x, U1, U3, rhs, lfp);
    k2_gemm<<<dim3(BT/32, KSPLIT), 128>>>(rhs, U2, Gp);
    k3_scores<<<BB, 576>>>(lfp, Gp, be, Ve, A);
    k4_out<<<dim3(NF4/128, BB), 128>>>((const float4*)x, A, (float4*)d_out);
}